// round 5
// baseline (speedup 1.0000x reference)
#include <cuda_runtime.h>
#include <cstdint>

#define NT 2048
#define CD 768
#define INFF  __int_as_float(0x7f800000)
#define NINFF __int_as_float(0xff800000)

// ---------------------------------------------------------------------------
// Device scratch (static allocations only)
// ---------------------------------------------------------------------------
__device__ float g_z1n[4 * NT * CD];
__device__ float g_z2n[4 * NT * CD];
__device__ float g_sq[2 * 4 * NT];          // z1 rows [0,8192), z2 rows [8192,16384)
__device__ float g_S[NT * NT];
__device__ int   g_neighCB[NT * 5];
__device__ int   g_negCB[NT * 5];
__device__ int   g_neighA[8 * NT * 5];
__device__ int   g_bofa[NT];
__device__ int   g_aofb[NT];
__device__ int   g_idxB[NT];
__device__ int   g_match[NT];
__device__ int   g_order[NT];
__device__ int   g_negc;
__device__ float g_rowbuf[NT];
__device__ float g_cntbuf[NT];
__device__ float g_slots[32];   // 0..7 cb means; 8..19 nrc sums; 20..31 nrc cnts

// ---------------------------------------------------------------------------
// Threefry-2x32 (20 rounds), matches JAX exactly
// ---------------------------------------------------------------------------
__host__ __device__ __forceinline__ void threefry2x32(
    uint32_t k0, uint32_t k1, uint32_t c0, uint32_t c1,
    uint32_t& o0, uint32_t& o1)
{
    uint32_t ks2 = k0 ^ k1 ^ 0x1BD11BDAu;
    uint32_t x0 = c0 + k0;
    uint32_t x1 = c1 + k1;
#define TF_R(r) { x0 += x1; x1 = (x1 << (r)) | (x1 >> (32 - (r))); x1 ^= x0; }
    TF_R(13) TF_R(15) TF_R(26) TF_R(6)
    x0 += k1;  x1 += ks2 + 1u;
    TF_R(17) TF_R(29) TF_R(16) TF_R(24)
    x0 += ks2; x1 += k0 + 2u;
    TF_R(13) TF_R(15) TF_R(26) TF_R(6)
    x0 += k0;  x1 += k1 + 3u;
    TF_R(17) TF_R(29) TF_R(16) TF_R(24)
    x0 += k1;  x1 += ks2 + 4u;
    TF_R(13) TF_R(15) TF_R(26) TF_R(6)
    x0 += ks2; x1 += k0 + 5u;
#undef TF_R
    o0 = x0; o1 = x1;
}

// Partitionable-mode random bits for 32-bit draws: counter (0, idx), o0^o1.
__host__ __device__ __forceinline__ uint32_t tf_bits(uint32_t k0, uint32_t k1, uint32_t idx) {
    uint32_t o0, o1;
    threefry2x32(k0, k1, 0u, idx, o0, o1);
    return o0 ^ o1;
}

// ---------------------------------------------------------------------------
// Normalize rows (both tensors) + squared norms. One warp per row.
// ---------------------------------------------------------------------------
__global__ void normalize_kernel(const float* __restrict__ z1,
                                 const float* __restrict__ z2) {
    int gw = (blockIdx.x * blockDim.x + threadIdx.x) >> 5;
    int lane = threadIdx.x & 31;
    if (gw >= 2 * 4 * NT) return;
    const float* src;
    float* dst;
    if (gw < 4 * NT) { src = z1 + (size_t)gw * CD; dst = g_z1n + (size_t)gw * CD; }
    else { int r = gw - 4 * NT; src = z2 + (size_t)r * CD; dst = g_z2n + (size_t)r * CD; }

    float a[24];
    float s = 0.f;
#pragma unroll
    for (int u = 0; u < 24; u++) { float v = src[lane + u * 32]; a[u] = v; s += v * v; }
#pragma unroll
    for (int off = 16; off; off >>= 1) s += __shfl_xor_sync(0xffffffffu, s, off);
    if (lane == 0) g_sq[gw] = s;
    float inv = rsqrtf(s + 1e-12f);
#pragma unroll
    for (int u = 0; u < 24; u++) dst[lane + u * 32] = a[u] * inv;
}

// ---------------------------------------------------------------------------
// GEMM: acc[i,j] = dot(A_row_i, B_row_j) over CD=768.
// mode 0: S = max(sqA[i]+sqB[j]-2*acc, 0)   mode 1: S = 1 - acc
// 128x128 tile, BK=16, 256 threads, 8x8 per thread.
// ---------------------------------------------------------------------------
__global__ __launch_bounds__(256, 2) void gemm_kernel(
    const float* __restrict__ A, const float* __restrict__ B,
    const float* __restrict__ sqA, const float* __restrict__ sqB,
    float* __restrict__ S, int mode)
{
    __shared__ float As[16][128];
    __shared__ float Bs[16][128];

    int tid = threadIdx.x;
    int tx = tid & 15;
    int ty = tid >> 4;
    int lr = tid >> 2;
    int lc = (tid & 3) << 2;

    const float* Ag = A + (size_t)(blockIdx.y * 128) * CD;
    const float* Bg = B + (size_t)(blockIdx.x * 128) * CD;

    float acc[8][8];
#pragma unroll
    for (int i = 0; i < 8; i++)
#pragma unroll
        for (int j = 0; j < 8; j++) acc[i][j] = 0.f;

    for (int kk = 0; kk < CD; kk += 16) {
        float4 a0 = *(const float4*)(Ag + (size_t)lr * CD + kk + lc);
        float4 a1 = *(const float4*)(Ag + (size_t)(lr + 64) * CD + kk + lc);
        float4 b0 = *(const float4*)(Bg + (size_t)lr * CD + kk + lc);
        float4 b1 = *(const float4*)(Bg + (size_t)(lr + 64) * CD + kk + lc);
        __syncthreads();
        As[lc + 0][lr] = a0.x; As[lc + 1][lr] = a0.y; As[lc + 2][lr] = a0.z; As[lc + 3][lr] = a0.w;
        As[lc + 0][lr + 64] = a1.x; As[lc + 1][lr + 64] = a1.y; As[lc + 2][lr + 64] = a1.z; As[lc + 3][lr + 64] = a1.w;
        Bs[lc + 0][lr] = b0.x; Bs[lc + 1][lr] = b0.y; Bs[lc + 2][lr] = b0.z; Bs[lc + 3][lr] = b0.w;
        Bs[lc + 0][lr + 64] = b1.x; Bs[lc + 1][lr + 64] = b1.y; Bs[lc + 2][lr + 64] = b1.z; Bs[lc + 3][lr + 64] = b1.w;
        __syncthreads();
#pragma unroll
        for (int k = 0; k < 16; k++) {
            float4 av0 = *(const float4*)(&As[k][ty * 8]);
            float4 av1 = *(const float4*)(&As[k][ty * 8 + 4]);
            float4 bv0 = *(const float4*)(&Bs[k][tx * 8]);
            float4 bv1 = *(const float4*)(&Bs[k][tx * 8 + 4]);
            float ar[8] = {av0.x, av0.y, av0.z, av0.w, av1.x, av1.y, av1.z, av1.w};
            float br[8] = {bv0.x, bv0.y, bv0.z, bv0.w, bv1.x, bv1.y, bv1.z, bv1.w};
#pragma unroll
            for (int i = 0; i < 8; i++)
#pragma unroll
                for (int j = 0; j < 8; j++) acc[i][j] += ar[i] * br[j];
        }
    }

    int rb = blockIdx.y * 128 + ty * 8;
    int cb = blockIdx.x * 128 + tx * 8;
    if (mode == 0) {
        float sr[8], sc[8];
#pragma unroll
        for (int i = 0; i < 8; i++) sr[i] = sqA[rb + i];
#pragma unroll
        for (int j = 0; j < 8; j++) sc[j] = sqB[cb + j];
#pragma unroll
        for (int i = 0; i < 8; i++)
#pragma unroll
            for (int j = 0; j < 8; j++)
                S[(size_t)(rb + i) * NT + cb + j] = fmaxf(sr[i] + sc[j] - 2.f * acc[i][j], 0.f);
    } else {
#pragma unroll
        for (int i = 0; i < 8; i++)
#pragma unroll
            for (int j = 0; j < 8; j++)
                S[(size_t)(rb + i) * NT + cb + j] = 1.f - acc[i][j];
    }
}

// ---------------------------------------------------------------------------
// Per-row 6 smallest (stable, lexicographic on (value, index)); emit indices
// 1..5 (drop self). One warp per row. Matches stable argsort[:,1:6].
// ---------------------------------------------------------------------------
__global__ void select6_kernel(const float* __restrict__ S, int* __restrict__ neigh) {
    int row = (blockIdx.x * blockDim.x + threadIdx.x) >> 5;
    int lane = threadIdx.x & 31;
    if (row >= NT) return;
    const float* r = S + (size_t)row * NT;

    float bv[6]; int bi[6];
#pragma unroll
    for (int u = 0; u < 6; u++) { bv[u] = INFF; bi[u] = 0x7fffffff; }

    for (int j = lane; j < NT; j += 32) {
        float v = r[j];
        if (v < bv[5] || (v == bv[5] && j < bi[5])) {
            int pos = 5;
            while (pos > 0 && (v < bv[pos - 1] || (v == bv[pos - 1] && j < bi[pos - 1]))) {
                bv[pos] = bv[pos - 1]; bi[pos] = bi[pos - 1]; pos--;
            }
            bv[pos] = v; bi[pos] = j;
        }
    }
    for (int t = 0; t < 6; t++) {
        float v = bv[0]; int id = bi[0];
#pragma unroll
        for (int off = 16; off; off >>= 1) {
            float ov = __shfl_down_sync(0xffffffffu, v, off);
            int oi = __shfl_down_sync(0xffffffffu, id, off);
            if (ov < v || (ov == v && oi < id)) { v = ov; id = oi; }
        }
        id = __shfl_sync(0xffffffffu, id, 0);
        if (bi[0] == id) {
#pragma unroll
            for (int u = 0; u < 5; u++) { bv[u] = bv[u + 1]; bi[u] = bi[u + 1]; }
            bv[5] = INFF; bi[5] = 0x7fffffff;
        }
        if (t > 0 && lane == 0) neigh[row * 5 + t - 1] = id;
    }
}

// ---------------------------------------------------------------------------
// Crossbrain negatives: top-5 largest uniforms per row (mask self + 5 neigh),
// ties -> lower index (lax.top_k). One warp per row.
// ---------------------------------------------------------------------------
__global__ void cbneg_kernel(uint32_t k0, uint32_t k1,
                             const int* __restrict__ neigh, int* __restrict__ neg) {
    int row = (blockIdx.x * blockDim.x + threadIdx.x) >> 5;
    int lane = threadIdx.x & 31;
    if (row >= NT) return;
    int n0 = neigh[row * 5 + 0], n1 = neigh[row * 5 + 1], n2 = neigh[row * 5 + 2],
        n3 = neigh[row * 5 + 3], n4 = neigh[row * 5 + 4];

    float bv[5]; int bi[5];
#pragma unroll
    for (int u = 0; u < 5; u++) { bv[u] = NINFF; bi[u] = 0x7fffffff; }

    for (int j = lane; j < NT; j += 32) {
        if (j == row || j == n0 || j == n1 || j == n2 || j == n3 || j == n4) continue;
        uint32_t bits = tf_bits(k0, k1, (uint32_t)(row * NT + j));
        float v = __uint_as_float((bits >> 9) | 0x3f800000u) - 1.0f;
        if (v > bv[4] || (v == bv[4] && j < bi[4])) {
            int pos = 4;
            while (pos > 0 && (v > bv[pos - 1] || (v == bv[pos - 1] && j < bi[pos - 1]))) {
                bv[pos] = bv[pos - 1]; bi[pos] = bi[pos - 1]; pos--;
            }
            bv[pos] = v; bi[pos] = j;
        }
    }
    for (int t = 0; t < 5; t++) {
        float v = bv[0]; int id = bi[0];
#pragma unroll
        for (int off = 16; off; off >>= 1) {
            float ov = __shfl_down_sync(0xffffffffu, v, off);
            int oi = __shfl_down_sync(0xffffffffu, id, off);
            if (ov > v || (ov == v && oi < id)) { v = ov; id = oi; }
        }
        id = __shfl_sync(0xffffffffu, id, 0);
        if (bi[0] == id) {
#pragma unroll
            for (int u = 0; u < 4; u++) { bv[u] = bv[u + 1]; bi[u] = bi[u + 1]; }
            bv[4] = NINFF; bi[4] = 0x7fffffff;
        }
        if (lane == 0) neg[row * 5 + t] = id;
    }
}

// ---------------------------------------------------------------------------
// Crossbrain per-row hinge sum. anchors = normalized "other" tensor.
// term_k = relu(clip(dot_neg) - clip(dot_pos) + 0.05)
// ---------------------------------------------------------------------------
__global__ void cbloss_kernel(const float* __restrict__ An,
                              const int* __restrict__ neigh,
                              const int* __restrict__ neg,
                              float* __restrict__ rowbuf) {
    int row = (blockIdx.x * blockDim.x + threadIdx.x) >> 5;
    int lane = threadIdx.x & 31;
    if (row >= NT) return;
    float a[24];
    const float* ar = An + (size_t)row * CD;
#pragma unroll
    for (int u = 0; u < 24; u++) a[u] = ar[lane + u * 32];
    float s = 0.f;
    for (int k = 0; k < 5; k++) {
        const float* pr = An + (size_t)neigh[row * 5 + k] * CD;
        const float* nr = An + (size_t)neg[row * 5 + k] * CD;
        float dp = 0.f, dn = 0.f;
#pragma unroll
        for (int u = 0; u < 24; u++) {
            dp += a[u] * pr[lane + u * 32];
            dn += a[u] * nr[lane + u * 32];
        }
#pragma unroll
        for (int off = 16; off; off >>= 1) {
            dp += __shfl_xor_sync(0xffffffffu, dp, off);
            dn += __shfl_xor_sync(0xffffffffu, dn, off);
        }
        float sp = fminf(fmaxf(dp, -1.f), 1.f);
        float sn = fminf(fmaxf(dn, -1.f), 1.f);
        s += fmaxf(sn - sp + 0.05f, 0.f);
    }
    if (lane == 0) rowbuf[row] = s;
}

// ---------------------------------------------------------------------------
// Row/col argmin (first occurrence)
// ---------------------------------------------------------------------------
__global__ void argmin_rows_kernel(const float* __restrict__ S, int* __restrict__ out) {
    int row = (blockIdx.x * blockDim.x + threadIdx.x) >> 5;
    int lane = threadIdx.x & 31;
    if (row >= NT) return;
    const float* r = S + (size_t)row * NT;
    float bv = INFF; int bi = 0x7fffffff;
    for (int j = lane; j < NT; j += 32) {
        float v = r[j];
        if (v < bv || (v == bv && j < bi)) { bv = v; bi = j; }
    }
#pragma unroll
    for (int off = 16; off; off >>= 1) {
        float ov = __shfl_down_sync(0xffffffffu, bv, off);
        int oi = __shfl_down_sync(0xffffffffu, bi, off);
        if (ov < bv || (ov == bv && oi < bi)) { bv = ov; bi = oi; }
    }
    if (lane == 0) out[row] = bi;
}

__global__ void argmin_cols_kernel(const float* __restrict__ S, int* __restrict__ out) {
    __shared__ float sv[32][33];
    __shared__ int   si[32][33];
    int tx = threadIdx.x, ty = threadIdx.y;
    int c = blockIdx.x * 32 + tx;
    float bv = INFF; int bi = 0x7fffffff;
    for (int r0 = 0; r0 < NT; r0 += 32) {
        int r = r0 + ty;
        float v = S[(size_t)r * NT + c];
        if (v < bv || (v == bv && r < bi)) { bv = v; bi = r; }
    }
    sv[ty][tx] = bv; si[ty][tx] = bi;
    __syncthreads();
    if (ty == 0) {
        float v = sv[0][tx]; int id = si[0][tx];
#pragma unroll
        for (int u = 1; u < 32; u++) {
            float ov = sv[u][tx]; int oi = si[u][tx];
            if (ov < v || (ov == v && oi < id)) { v = ov; id = oi; }
        }
        out[c] = id;
    }
}

// ---------------------------------------------------------------------------
// Mutual matching
// ---------------------------------------------------------------------------
__global__ void mutual_a_kernel(const int* __restrict__ bofa, const int* __restrict__ aofb,
                                int* __restrict__ idxB, int* __restrict__ match) {
    int i = blockIdx.x * blockDim.x + threadIdx.x;
    if (i >= NT) return;
    match[i] = 0;
    int b = bofa[i];
    idxB[i] = (aofb[b] == i) ? b : -1;
}
__global__ void mutual_b_kernel(const int* __restrict__ idxB, int* __restrict__ match) {
    int i = blockIdx.x * blockDim.x + threadIdx.x;
    if (i >= NT) return;
    int b = idxB[i];
    if (b >= 0) match[b] = 1;   // unique writer per b (mutual match is a bijection)
}

// ---------------------------------------------------------------------------
// Stable bool argsort: unmatched indices first (ascending), then matched.
// One block, 256 threads x 8 elems.
// ---------------------------------------------------------------------------
__global__ void order_kernel(const int* __restrict__ match, int* __restrict__ order,
                             int* __restrict__ negc) {
    __shared__ int cnt[256];
    __shared__ int excl[257];
    int t = threadIdx.x;
    int base = t * 8;
    int m[8]; int c = 0;
#pragma unroll
    for (int u = 0; u < 8; u++) { m[u] = match[base + u]; c += (m[u] == 0); }
    cnt[t] = c;
    __syncthreads();
    if (t == 0) {
        int s = 0;
        for (int i = 0; i < 256; i++) { excl[i] = s; s += cnt[i]; }
        excl[256] = s;
    }
    __syncthreads();
    int Utot = excl[256];
    int u = excl[t];
    int mm = base - u;
#pragma unroll
    for (int x = 0; x < 8; x++) {
        if (m[x] == 0) order[u++] = base + x;
        else           order[Utot + mm++] = base + x;
    }
    if (t == 0) *negc = (Utot > 0) ? Utot : 1;
}

// ---------------------------------------------------------------------------
// NRC per-token loss. One warp per token.
// ---------------------------------------------------------------------------
__global__ void nrcloss_kernel(const float* __restrict__ Bn,
                               const int* __restrict__ idxB,
                               const int* __restrict__ neighA,
                               const int* __restrict__ order,
                               const int* __restrict__ negcp,
                               uint32_t k0, uint32_t k1,
                               float* __restrict__ rowbuf, float* __restrict__ cntbuf) {
    int i = (blockIdx.x * blockDim.x + threadIdx.x) >> 5;
    int lane = threadIdx.x & 31;
    if (i >= NT) return;
    int ib = idxB[i];
    int uB = ib < 0 ? 0 : ib;
    int nc = *negcp;
    float a[24];
    const float* ar = Bn + (size_t)uB * CD;
#pragma unroll
    for (int u = 0; u < 24; u++) a[u] = ar[lane + u * 32];
    float hs = 0.f; int npos = 0;
    for (int k = 0; k < 5; k++) {
        int pb = idxB[neighA[i * 5 + k]];
        uint32_t bits = tf_bits(k0, k1, 10240u + (uint32_t)(i * 5 + k));
        int nb = order[(int)(bits & 2047u) % nc];
        const float* pr = Bn + (size_t)(pb < 0 ? 0 : pb) * CD;
        const float* nr = Bn + (size_t)nb * CD;
        float dp = 0.f, dn = 0.f;
#pragma unroll
        for (int u = 0; u < 24; u++) {
            dp += a[u] * pr[lane + u * 32];
            dn += a[u] * nr[lane + u * 32];
        }
#pragma unroll
        for (int off = 16; off; off >>= 1) {
            dp += __shfl_xor_sync(0xffffffffu, dp, off);
            dn += __shfl_xor_sync(0xffffffffu, dn, off);
        }
        // d_pos - d_neg = (1-dp)-(1-dn) = dn - dp ; margin 0.4 ; masked by pos
        if (pb >= 0) { hs += fmaxf(dn - dp + 0.4f, 0.f); npos++; }
    }
    if (lane == 0) {
        float per = hs / (float)(npos > 0 ? npos : 1);
        int valid = (ib >= 0) && (npos > 0);
        rowbuf[i] = valid ? per : 0.f;
        cntbuf[i] = valid ? 1.f : 0.f;
    }
}

// ---------------------------------------------------------------------------
// Deterministic fixed-tree reduction of 2048 floats -> *dst = sum*scale
// ---------------------------------------------------------------------------
__global__ void reduce_kernel(const float* __restrict__ buf, float* __restrict__ dst, float scale) {
    __shared__ float sh[1024];
    int t = threadIdx.x;
    sh[t] = buf[t] + buf[t + 1024];
    __syncthreads();
    for (int s = 512; s; s >>= 1) {
        if (t < s) sh[t] += sh[t + s];
        __syncthreads();
    }
    if (t == 0) *dst = sh[0] * scale;
}

// ---------------------------------------------------------------------------
// Final combine
// ---------------------------------------------------------------------------
__global__ void final_kernel(float* __restrict__ out) {
    float l2 = 0.f;
    for (int i = 0; i < 8; i++) l2 += g_slots[i];
    l2 *= 0.25f;
    float l3 = 0.f;
    for (int s = 0; s < 2; s++) {
        float acc = 0.f;
        for (int j = 0; j < 6; j++) {
            int pi = s * 6 + j;
            float cn = g_slots[20 + pi];
            float sm = g_slots[8 + pi];
            acc += (cn > 0.f) ? sm / fmaxf(cn, 1.f) : 0.f;
        }
        l3 += acc / 6.f;
    }
    out[0] = 10.f * l2 + 10.f * l3;
}

// ---------------------------------------------------------------------------
// Host: MT19937 (numpy legacy) for pair selection
// ---------------------------------------------------------------------------
namespace {
struct HostMT { uint32_t mt[624]; int pos; };
static void mt_seed(HostMT& s, uint32_t seed) {
    for (int p = 0; p < 624; p++) {
        s.mt[p] = seed;
        seed = 1812433253u * (seed ^ (seed >> 30)) + (uint32_t)p + 1u;
    }
    s.pos = 624;
}
static uint32_t mt_next(HostMT& s) {
    if (s.pos == 624) {
        for (int i = 0; i < 624; i++) {
            uint32_t y = (s.mt[i] & 0x80000000u) | (s.mt[(i + 1) % 624] & 0x7fffffffu);
            s.mt[i] = s.mt[(i + 397) % 624] ^ (y >> 1) ^ ((y & 1u) ? 0x9908b0dfu : 0u);
        }
        s.pos = 0;
    }
    uint32_t y = s.mt[s.pos++];
    y ^= y >> 11;
    y ^= (y << 7) & 0x9d2c5680u;
    y ^= (y << 15) & 0xefc60000u;
    y ^= y >> 18;
    return y;
}
static uint32_t mt_interval(HostMT& s, uint32_t mx) {   // uniform in [0, mx]
    if (mx == 0) return 0;
    uint32_t mask = mx;
    mask |= mask >> 1; mask |= mask >> 2; mask |= mask >> 4;
    mask |= mask >> 8; mask |= mask >> 16;
    uint32_t v;
    while ((v = (mt_next(s) & mask)) > mx) {}
    return v;
}
static void perm12(uint32_t seed, int* out) {
    HostMT s; mt_seed(s, seed);
    for (int i = 0; i < 12; i++) out[i] = i;
    for (int i = 11; i > 0; i--) {
        int j = (int)mt_interval(s, (uint32_t)i);
        int t = out[i]; out[i] = out[j]; out[j] = t;
    }
}
}  // namespace

// ---------------------------------------------------------------------------
// kernel_launch
// ---------------------------------------------------------------------------
extern "C" void kernel_launch(void* const* d_in, const int* in_sizes, int n_in,
                              void* d_out, int out_size) {
    const float* z1 = (const float*)d_in[0];
    const float* z2 = (const float*)d_in[1];
    float* out = (float*)d_out;

    float *z1n, *z2n, *sq, *S, *rowbuf, *cntbuf, *slots;
    int *neighCB, *negCB, *neighA, *bofa, *aofb, *idxB, *match, *order, *negc;
    cudaGetSymbolAddress((void**)&z1n, g_z1n);
    cudaGetSymbolAddress((void**)&z2n, g_z2n);
    cudaGetSymbolAddress((void**)&sq, g_sq);
    cudaGetSymbolAddress((void**)&S, g_S);
    cudaGetSymbolAddress((void**)&rowbuf, g_rowbuf);
    cudaGetSymbolAddress((void**)&cntbuf, g_cntbuf);
    cudaGetSymbolAddress((void**)&slots, g_slots);
    cudaGetSymbolAddress((void**)&neighCB, g_neighCB);
    cudaGetSymbolAddress((void**)&negCB, g_negCB);
    cudaGetSymbolAddress((void**)&neighA, g_neighA);
    cudaGetSymbolAddress((void**)&bofa, g_bofa);
    cudaGetSymbolAddress((void**)&aofb, g_aofb);
    cudaGetSymbolAddress((void**)&idxB, g_idxB);
    cudaGetSymbolAddress((void**)&match, g_match);
    cudaGetSymbolAddress((void**)&order, g_order);
    cudaGetSymbolAddress((void**)&negc, g_negc);

    // --- key derivation (partitionable threefry): child i of split = TF(key,(0,i))
    uint32_t ck[4][2];
    for (int i = 0; i < 4; i++)
        threefry2x32(0u, 42u, 0u, (uint32_t)i, ck[i][0], ck[i][1]);
    uint32_t cbk[2][4][2];
    for (int b = 0; b < 4; b++) {
        threefry2x32(ck[0][0], ck[0][1], 0u, (uint32_t)b, cbk[0][b][0], cbk[0][b][1]);
        threefry2x32(ck[1][0], ck[1][1], 0u, (uint32_t)b, cbk[1][b][0], cbk[1][b][1]);
    }
    uint32_t kp[12][2];
    for (int j = 0; j < 6; j++) {
        threefry2x32(ck[2][0], ck[2][1], 0u, (uint32_t)j, kp[j][0], kp[j][1]);
        threefry2x32(ck[3][0], ck[3][1], 0u, (uint32_t)j, kp[6 + j][0], kp[6 + j][1]);
    }

    // --- pair selection (numpy MT19937, seeds 0 and 1)
    int allp[12][2];
    { int t = 0;
      for (int p = 0; p < 4; p++)
          for (int q = 0; q < 4; q++)
              if (p != q) { allp[t][0] = p; allp[t][1] = q; t++; } }
    int pairs[12][2];
    int perm[12];
    perm12(0u, perm);
    for (int j = 0; j < 6; j++) { pairs[j][0] = allp[perm[j]][0]; pairs[j][1] = allp[perm[j]][1]; }
    perm12(1u, perm);
    for (int j = 0; j < 6; j++) { pairs[6 + j][0] = allp[perm[j]][0]; pairs[6 + j][1] = allp[perm[j]][1]; }

    const size_t MAT = (size_t)NT * CD;

    // --- normalize + squared norms
    normalize_kernel<<<2048, 256>>>(z1, z2);

    // --- crossbrain: 8 combos
    for (int d = 0; d < 2; d++) {
        for (int b = 0; b < 4; b++) {
            const float* Araw = (d == 0 ? z1 : z2) + (size_t)b * MAT;
            const float* anch = (d == 0 ? z2n : z1n) + (size_t)b * MAT;
            const float* sqp = sq + d * 4 * NT + b * NT;
            gemm_kernel<<<dim3(16, 16), 256>>>(Araw, Araw, sqp, sqp, S, 0);
            select6_kernel<<<256, 256>>>(S, neighCB);
            cbneg_kernel<<<256, 256>>>(cbk[d][b][0], cbk[d][b][1], neighCB, negCB);
            cbloss_kernel<<<256, 256>>>(anch, neighCB, negCB, rowbuf);
            reduce_kernel<<<1, 1024>>>(rowbuf, slots + d * 4 + b, 1.0f / 10240.0f);
        }
    }

    // --- DA neighbor cache (cos-dist self KNN of A side), dedup across pairs
    bool need[8] = {false, false, false, false, false, false, false, false};
    for (int pi = 0; pi < 12; pi++) need[(pi / 6) * 4 + pairs[pi][0]] = true;
    for (int s = 0; s < 8; s++) {
        if (!need[s]) continue;
        const float* An = (s < 4 ? z1n : z2n) + (size_t)(s & 3) * MAT;
        gemm_kernel<<<dim3(16, 16), 256>>>(An, An, sq, sq, S, 1);
        select6_kernel<<<256, 256>>>(S, neighA + (size_t)s * NT * 5);
    }

    // --- NRC: 12 pair combos
    for (int pi = 0; pi < 12; pi++) {
        int side = pi / 6, p = pairs[pi][0], q = pairs[pi][1];
        const float* An = (side == 0 ? z1n : z2n) + (size_t)p * MAT;
        const float* Bn = (side == 0 ? z2n : z1n) + (size_t)q * MAT;
        gemm_kernel<<<dim3(16, 16), 256>>>(An, Bn, sq, sq, S, 1);
        argmin_rows_kernel<<<256, 256>>>(S, bofa);
        argmin_cols_kernel<<<64, dim3(32, 32)>>>(S, aofb);
        mutual_a_kernel<<<8, 256>>>(bofa, aofb, idxB, match);
        mutual_b_kernel<<<8, 256>>>(idxB, match);
        order_kernel<<<1, 256>>>(match, order, negc);
        nrcloss_kernel<<<256, 256>>>(Bn, idxB, neighA + (size_t)((side * 4 + p)) * NT * 5,
                                     order, negc, kp[pi][0], kp[pi][1], rowbuf, cntbuf);
        reduce_kernel<<<1, 1024>>>(rowbuf, slots + 8 + pi, 1.0f);
        reduce_kernel<<<1, 1024>>>(cntbuf, slots + 20 + pi, 1.0f);
    }

    // --- combine
    final_kernel<<<1, 1>>>(out);
}

// round 6
// speedup vs baseline: 1.0049x; 1.0049x over previous
#include <cuda_runtime.h>
#include <cstdint>

#define NT 2048
#define CD 768
#define INFF  __int_as_float(0x7f800000)
#define NINFF __int_as_float(0xff800000)

// ---------------------------------------------------------------------------
// Device scratch (static allocations only)
// ---------------------------------------------------------------------------
__device__ float g_z1n[4 * NT * CD];
__device__ float g_z2n[4 * NT * CD];
__device__ float g_sq[2 * 4 * NT];          // z1 rows [0,8192), z2 rows [8192,16384)
__device__ float g_S[NT * NT];
__device__ int   g_neighCB[NT * 5];
__device__ int   g_negCB[NT * 5];
__device__ int   g_neighA[8 * NT * 5];
__device__ int   g_bofa[NT];
__device__ int   g_aofb[NT];
__device__ int   g_idxB[NT];
__device__ int   g_match[NT];
__device__ int   g_order[NT];
__device__ int   g_negc;
__device__ float g_rowbuf[NT];
__device__ float g_cntbuf[NT];
__device__ float g_slots[32];   // 0..7 cb means; 8..19 nrc sums; 20..31 nrc cnts

// ---------------------------------------------------------------------------
// Threefry-2x32 (20 rounds), matches JAX exactly
// ---------------------------------------------------------------------------
__host__ __device__ __forceinline__ void threefry2x32(
    uint32_t k0, uint32_t k1, uint32_t c0, uint32_t c1,
    uint32_t& o0, uint32_t& o1)
{
    uint32_t ks2 = k0 ^ k1 ^ 0x1BD11BDAu;
    uint32_t x0 = c0 + k0;
    uint32_t x1 = c1 + k1;
#define TF_R(r) { x0 += x1; x1 = (x1 << (r)) | (x1 >> (32 - (r))); x1 ^= x0; }
    TF_R(13) TF_R(15) TF_R(26) TF_R(6)
    x0 += k1;  x1 += ks2 + 1u;
    TF_R(17) TF_R(29) TF_R(16) TF_R(24)
    x0 += ks2; x1 += k0 + 2u;
    TF_R(13) TF_R(15) TF_R(26) TF_R(6)
    x0 += k0;  x1 += k1 + 3u;
    TF_R(17) TF_R(29) TF_R(16) TF_R(24)
    x0 += k1;  x1 += ks2 + 4u;
    TF_R(13) TF_R(15) TF_R(26) TF_R(6)
    x0 += ks2; x1 += k0 + 5u;
#undef TF_R
    o0 = x0; o1 = x1;
}

// Partitionable-mode random bits for 32-bit draws: counter (0, idx), o0^o1.
__host__ __device__ __forceinline__ uint32_t tf_bits(uint32_t k0, uint32_t k1, uint32_t idx) {
    uint32_t o0, o1;
    threefry2x32(k0, k1, 0u, idx, o0, o1);
    return o0 ^ o1;
}

// ---------------------------------------------------------------------------
// Normalize rows (both tensors) + squared norms. One warp per row.
// ---------------------------------------------------------------------------
__global__ void normalize_kernel(const float* __restrict__ z1,
                                 const float* __restrict__ z2) {
    int gw = (blockIdx.x * blockDim.x + threadIdx.x) >> 5;
    int lane = threadIdx.x & 31;
    if (gw >= 2 * 4 * NT) return;
    const float* src;
    float* dst;
    if (gw < 4 * NT) { src = z1 + (size_t)gw * CD; dst = g_z1n + (size_t)gw * CD; }
    else { int r = gw - 4 * NT; src = z2 + (size_t)r * CD; dst = g_z2n + (size_t)r * CD; }

    float a[24];
    float s = 0.f;
#pragma unroll
    for (int u = 0; u < 24; u++) { float v = src[lane + u * 32]; a[u] = v; s += v * v; }
#pragma unroll
    for (int off = 16; off; off >>= 1) s += __shfl_xor_sync(0xffffffffu, s, off);
    if (lane == 0) g_sq[gw] = s;
    float inv = rsqrtf(s + 1e-12f);
#pragma unroll
    for (int u = 0; u < 24; u++) dst[lane + u * 32] = a[u] * inv;
}

// ---------------------------------------------------------------------------
// GEMM: acc[i,j] = dot(A_row_i, B_row_j) over CD=768.
// mode 0: S = max(sqA[i]+sqB[j]-2*acc, 0)   mode 1: S = 1 - acc
// 128x128 tile, BK=16, 256 threads, 8x8 per thread.
// ---------------------------------------------------------------------------
__global__ __launch_bounds__(256, 2) void gemm_kernel(
    const float* __restrict__ A, const float* __restrict__ B,
    const float* __restrict__ sqA, const float* __restrict__ sqB,
    float* __restrict__ S, int mode)
{
    __shared__ float As[16][128];
    __shared__ float Bs[16][128];

    int tid = threadIdx.x;
    int tx = tid & 15;
    int ty = tid >> 4;
    int lr = tid >> 2;
    int lc = (tid & 3) << 2;

    const float* Ag = A + (size_t)(blockIdx.y * 128) * CD;
    const float* Bg = B + (size_t)(blockIdx.x * 128) * CD;

    float acc[8][8];
#pragma unroll
    for (int i = 0; i < 8; i++)
#pragma unroll
        for (int j = 0; j < 8; j++) acc[i][j] = 0.f;

    for (int kk = 0; kk < CD; kk += 16) {
        float4 a0 = *(const float4*)(Ag + (size_t)lr * CD + kk + lc);
        float4 a1 = *(const float4*)(Ag + (size_t)(lr + 64) * CD + kk + lc);
        float4 b0 = *(const float4*)(Bg + (size_t)lr * CD + kk + lc);
        float4 b1 = *(const float4*)(Bg + (size_t)(lr + 64) * CD + kk + lc);
        __syncthreads();
        As[lc + 0][lr] = a0.x; As[lc + 1][lr] = a0.y; As[lc + 2][lr] = a0.z; As[lc + 3][lr] = a0.w;
        As[lc + 0][lr + 64] = a1.x; As[lc + 1][lr + 64] = a1.y; As[lc + 2][lr + 64] = a1.z; As[lc + 3][lr + 64] = a1.w;
        Bs[lc + 0][lr] = b0.x; Bs[lc + 1][lr] = b0.y; Bs[lc + 2][lr] = b0.z; Bs[lc + 3][lr] = b0.w;
        Bs[lc + 0][lr + 64] = b1.x; Bs[lc + 1][lr + 64] = b1.y; Bs[lc + 2][lr + 64] = b1.z; Bs[lc + 3][lr + 64] = b1.w;
        __syncthreads();
#pragma unroll
        for (int k = 0; k < 16; k++) {
            float4 av0 = *(const float4*)(&As[k][ty * 8]);
            float4 av1 = *(const float4*)(&As[k][ty * 8 + 4]);
            float4 bv0 = *(const float4*)(&Bs[k][tx * 8]);
            float4 bv1 = *(const float4*)(&Bs[k][tx * 8 + 4]);
            float ar[8] = {av0.x, av0.y, av0.z, av0.w, av1.x, av1.y, av1.z, av1.w};
            float br[8] = {bv0.x, bv0.y, bv0.z, bv0.w, bv1.x, bv1.y, bv1.z, bv1.w};
#pragma unroll
            for (int i = 0; i < 8; i++)
#pragma unroll
                for (int j = 0; j < 8; j++) acc[i][j] += ar[i] * br[j];
        }
    }

    int rb = blockIdx.y * 128 + ty * 8;
    int cb = blockIdx.x * 128 + tx * 8;
    if (mode == 0) {
        float sr[8], sc[8];
#pragma unroll
        for (int i = 0; i < 8; i++) sr[i] = sqA[rb + i];
#pragma unroll
        for (int j = 0; j < 8; j++) sc[j] = sqB[cb + j];
#pragma unroll
        for (int i = 0; i < 8; i++)
#pragma unroll
            for (int j = 0; j < 8; j++)
                S[(size_t)(rb + i) * NT + cb + j] = fmaxf(sr[i] + sc[j] - 2.f * acc[i][j], 0.f);
    } else {
#pragma unroll
        for (int i = 0; i < 8; i++)
#pragma unroll
            for (int j = 0; j < 8; j++)
                S[(size_t)(rb + i) * NT + cb + j] = 1.f - acc[i][j];
    }
}

// ---------------------------------------------------------------------------
// Per-row 6 smallest (stable, lexicographic on (value, index)); emit indices
// 1..5 (drop self). One warp per row. Matches stable argsort[:,1:6].
// ---------------------------------------------------------------------------
__global__ void select6_kernel(const float* __restrict__ S, int* __restrict__ neigh) {
    int row = (blockIdx.x * blockDim.x + threadIdx.x) >> 5;
    int lane = threadIdx.x & 31;
    if (row >= NT) return;
    const float* r = S + (size_t)row * NT;

    float bv[6]; int bi[6];
#pragma unroll
    for (int u = 0; u < 6; u++) { bv[u] = INFF; bi[u] = 0x7fffffff; }

    for (int j = lane; j < NT; j += 32) {
        float v = r[j];
        if (v < bv[5] || (v == bv[5] && j < bi[5])) {
            int pos = 5;
            while (pos > 0 && (v < bv[pos - 1] || (v == bv[pos - 1] && j < bi[pos - 1]))) {
                bv[pos] = bv[pos - 1]; bi[pos] = bi[pos - 1]; pos--;
            }
            bv[pos] = v; bi[pos] = j;
        }
    }
    for (int t = 0; t < 6; t++) {
        float v = bv[0]; int id = bi[0];
#pragma unroll
        for (int off = 16; off; off >>= 1) {
            float ov = __shfl_down_sync(0xffffffffu, v, off);
            int oi = __shfl_down_sync(0xffffffffu, id, off);
            if (ov < v || (ov == v && oi < id)) { v = ov; id = oi; }
        }
        id = __shfl_sync(0xffffffffu, id, 0);
        if (bi[0] == id) {
#pragma unroll
            for (int u = 0; u < 5; u++) { bv[u] = bv[u + 1]; bi[u] = bi[u + 1]; }
            bv[5] = INFF; bi[5] = 0x7fffffff;
        }
        if (t > 0 && lane == 0) neigh[row * 5 + t - 1] = id;
    }
}

// ---------------------------------------------------------------------------
// Crossbrain negatives: top-5 largest uniforms per row (mask self + 5 neigh),
// ties -> lower index (lax.top_k). One warp per row.
// ---------------------------------------------------------------------------
__global__ void cbneg_kernel(uint32_t k0, uint32_t k1,
                             const int* __restrict__ neigh, int* __restrict__ neg) {
    int row = (blockIdx.x * blockDim.x + threadIdx.x) >> 5;
    int lane = threadIdx.x & 31;
    if (row >= NT) return;
    int n0 = neigh[row * 5 + 0], n1 = neigh[row * 5 + 1], n2 = neigh[row * 5 + 2],
        n3 = neigh[row * 5 + 3], n4 = neigh[row * 5 + 4];

    float bv[5]; int bi[5];
#pragma unroll
    for (int u = 0; u < 5; u++) { bv[u] = NINFF; bi[u] = 0x7fffffff; }

    for (int j = lane; j < NT; j += 32) {
        if (j == row || j == n0 || j == n1 || j == n2 || j == n3 || j == n4) continue;
        uint32_t bits = tf_bits(k0, k1, (uint32_t)(row * NT + j));
        float v = __uint_as_float((bits >> 9) | 0x3f800000u) - 1.0f;
        if (v > bv[4] || (v == bv[4] && j < bi[4])) {
            int pos = 4;
            while (pos > 0 && (v > bv[pos - 1] || (v == bv[pos - 1] && j < bi[pos - 1]))) {
                bv[pos] = bv[pos - 1]; bi[pos] = bi[pos - 1]; pos--;
            }
            bv[pos] = v; bi[pos] = j;
        }
    }
    for (int t = 0; t < 5; t++) {
        float v = bv[0]; int id = bi[0];
#pragma unroll
        for (int off = 16; off; off >>= 1) {
            float ov = __shfl_down_sync(0xffffffffu, v, off);
            int oi = __shfl_down_sync(0xffffffffu, id, off);
            if (ov > v || (ov == v && oi < id)) { v = ov; id = oi; }
        }
        id = __shfl_sync(0xffffffffu, id, 0);
        if (bi[0] == id) {
#pragma unroll
            for (int u = 0; u < 4; u++) { bv[u] = bv[u + 1]; bi[u] = bi[u + 1]; }
            bv[4] = NINFF; bi[4] = 0x7fffffff;
        }
        if (lane == 0) neg[row * 5 + t] = id;
    }
}

// ---------------------------------------------------------------------------
// Crossbrain per-row hinge sum. anchors = normalized "other" tensor.
// term_k = relu(clip(dot_neg) - clip(dot_pos) + 0.05)
// ---------------------------------------------------------------------------
__global__ void cbloss_kernel(const float* __restrict__ An,
                              const int* __restrict__ neigh,
                              const int* __restrict__ neg,
                              float* __restrict__ rowbuf) {
    int row = (blockIdx.x * blockDim.x + threadIdx.x) >> 5;
    int lane = threadIdx.x & 31;
    if (row >= NT) return;
    float a[24];
    const float* ar = An + (size_t)row * CD;
#pragma unroll
    for (int u = 0; u < 24; u++) a[u] = ar[lane + u * 32];
    float s = 0.f;
    for (int k = 0; k < 5; k++) {
        const float* pr = An + (size_t)neigh[row * 5 + k] * CD;
        const float* nr = An + (size_t)neg[row * 5 + k] * CD;
        float dp = 0.f, dn = 0.f;
#pragma unroll
        for (int u = 0; u < 24; u++) {
            dp += a[u] * pr[lane + u * 32];
            dn += a[u] * nr[lane + u * 32];
        }
#pragma unroll
        for (int off = 16; off; off >>= 1) {
            dp += __shfl_xor_sync(0xffffffffu, dp, off);
            dn += __shfl_xor_sync(0xffffffffu, dn, off);
        }
        float sp = fminf(fmaxf(dp, -1.f), 1.f);
        float sn = fminf(fmaxf(dn, -1.f), 1.f);
        s += fmaxf(sn - sp + 0.05f, 0.f);
    }
    if (lane == 0) rowbuf[row] = s;
}

// ---------------------------------------------------------------------------
// Row/col argmin (first occurrence)
// ---------------------------------------------------------------------------
__global__ void argmin_rows_kernel(const float* __restrict__ S, int* __restrict__ out) {
    int row = (blockIdx.x * blockDim.x + threadIdx.x) >> 5;
    int lane = threadIdx.x & 31;
    if (row >= NT) return;
    const float* r = S + (size_t)row * NT;
    float bv = INFF; int bi = 0x7fffffff;
    for (int j = lane; j < NT; j += 32) {
        float v = r[j];
        if (v < bv || (v == bv && j < bi)) { bv = v; bi = j; }
    }
#pragma unroll
    for (int off = 16; off; off >>= 1) {
        float ov = __shfl_down_sync(0xffffffffu, bv, off);
        int oi = __shfl_down_sync(0xffffffffu, bi, off);
        if (ov < bv || (ov == bv && oi < bi)) { bv = ov; bi = oi; }
    }
    if (lane == 0) out[row] = bi;
}

__global__ void argmin_cols_kernel(const float* __restrict__ S, int* __restrict__ out) {
    __shared__ float sv[32][33];
    __shared__ int   si[32][33];
    int tx = threadIdx.x, ty = threadIdx.y;
    int c = blockIdx.x * 32 + tx;
    float bv = INFF; int bi = 0x7fffffff;
    for (int r0 = 0; r0 < NT; r0 += 32) {
        int r = r0 + ty;
        float v = S[(size_t)r * NT + c];
        if (v < bv || (v == bv && r < bi)) { bv = v; bi = r; }
    }
    sv[ty][tx] = bv; si[ty][tx] = bi;
    __syncthreads();
    if (ty == 0) {
        float v = sv[0][tx]; int id = si[0][tx];
#pragma unroll
        for (int u = 1; u < 32; u++) {
            float ov = sv[u][tx]; int oi = si[u][tx];
            if (ov < v || (ov == v && oi < id)) { v = ov; id = oi; }
        }
        out[c] = id;
    }
}

// ---------------------------------------------------------------------------
// Mutual matching
// ---------------------------------------------------------------------------
__global__ void mutual_a_kernel(const int* __restrict__ bofa, const int* __restrict__ aofb,
                                int* __restrict__ idxB, int* __restrict__ match) {
    int i = blockIdx.x * blockDim.x + threadIdx.x;
    if (i >= NT) return;
    match[i] = 0;
    int b = bofa[i];
    idxB[i] = (aofb[b] == i) ? b : -1;
}
__global__ void mutual_b_kernel(const int* __restrict__ idxB, int* __restrict__ match) {
    int i = blockIdx.x * blockDim.x + threadIdx.x;
    if (i >= NT) return;
    int b = idxB[i];
    if (b >= 0) match[b] = 1;   // unique writer per b (mutual match is a bijection)
}

// ---------------------------------------------------------------------------
// Stable bool argsort: unmatched indices first (ascending), then matched.
// One block, 256 threads x 8 elems.
// ---------------------------------------------------------------------------
__global__ void order_kernel(const int* __restrict__ match, int* __restrict__ order,
                             int* __restrict__ negc) {
    __shared__ int cnt[256];
    __shared__ int excl[257];
    int t = threadIdx.x;
    int base = t * 8;
    int m[8]; int c = 0;
#pragma unroll
    for (int u = 0; u < 8; u++) { m[u] = match[base + u]; c += (m[u] == 0); }
    cnt[t] = c;
    __syncthreads();
    if (t == 0) {
        int s = 0;
        for (int i = 0; i < 256; i++) { excl[i] = s; s += cnt[i]; }
        excl[256] = s;
    }
    __syncthreads();
    int Utot = excl[256];
    int u = excl[t];
    int mm = base - u;
#pragma unroll
    for (int x = 0; x < 8; x++) {
        if (m[x] == 0) order[u++] = base + x;
        else           order[Utot + mm++] = base + x;
    }
    if (t == 0) *negc = (Utot > 0) ? Utot : 1;
}

// ---------------------------------------------------------------------------
// NRC per-token loss. One warp per token.
// ---------------------------------------------------------------------------
__global__ void nrcloss_kernel(const float* __restrict__ Bn,
                               const int* __restrict__ idxB,
                               const int* __restrict__ neighA,
                               const int* __restrict__ order,
                               const int* __restrict__ negcp,
                               uint32_t k0, uint32_t k1,
                               float* __restrict__ rowbuf, float* __restrict__ cntbuf) {
    int i = (blockIdx.x * blockDim.x + threadIdx.x) >> 5;
    int lane = threadIdx.x & 31;
    if (i >= NT) return;
    int ib = idxB[i];
    int uB = ib < 0 ? 0 : ib;
    int nc = *negcp;
    float a[24];
    const float* ar = Bn + (size_t)uB * CD;
#pragma unroll
    for (int u = 0; u < 24; u++) a[u] = ar[lane + u * 32];
    float hs = 0.f; int npos = 0;
    for (int k = 0; k < 5; k++) {
        int pb = idxB[neighA[i * 5 + k]];
        uint32_t bits = tf_bits(k0, k1, 10240u + (uint32_t)(i * 5 + k));
        int nb = order[(int)(bits & 2047u) % nc];
        const float* pr = Bn + (size_t)(pb < 0 ? 0 : pb) * CD;
        const float* nr = Bn + (size_t)nb * CD;
        float dp = 0.f, dn = 0.f;
#pragma unroll
        for (int u = 0; u < 24; u++) {
            dp += a[u] * pr[lane + u * 32];
            dn += a[u] * nr[lane + u * 32];
        }
#pragma unroll
        for (int off = 16; off; off >>= 1) {
            dp += __shfl_xor_sync(0xffffffffu, dp, off);
            dn += __shfl_xor_sync(0xffffffffu, dn, off);
        }
        // d_pos - d_neg = (1-dp)-(1-dn) = dn - dp ; margin 0.4 ; masked by pos
        if (pb >= 0) { hs += fmaxf(dn - dp + 0.4f, 0.f); npos++; }
    }
    if (lane == 0) {
        float per = hs / (float)(npos > 0 ? npos : 1);
        int valid = (ib >= 0) && (npos > 0);
        rowbuf[i] = valid ? per : 0.f;
        cntbuf[i] = valid ? 1.f : 0.f;
    }
}

// ---------------------------------------------------------------------------
// Deterministic fixed-tree reduction of 2048 floats -> *dst = sum*scale
// ---------------------------------------------------------------------------
__global__ void reduce_kernel(const float* __restrict__ buf, float* __restrict__ dst, float scale) {
    __shared__ float sh[1024];
    int t = threadIdx.x;
    sh[t] = buf[t] + buf[t + 1024];
    __syncthreads();
    for (int s = 512; s; s >>= 1) {
        if (t < s) sh[t] += sh[t + s];
        __syncthreads();
    }
    if (t == 0) *dst = sh[0] * scale;
}

// ---------------------------------------------------------------------------
// Final combine
// ---------------------------------------------------------------------------
__global__ void final_kernel(float* __restrict__ out) {
    float l2 = 0.f;
    for (int i = 0; i < 8; i++) l2 += g_slots[i];
    l2 *= 0.25f;
    float l3 = 0.f;
    for (int s = 0; s < 2; s++) {
        float acc = 0.f;
        for (int j = 0; j < 6; j++) {
            int pi = s * 6 + j;
            float cn = g_slots[20 + pi];
            float sm = g_slots[8 + pi];
            acc += (cn > 0.f) ? sm / fmaxf(cn, 1.f) : 0.f;
        }
        l3 += acc / 6.f;
    }
    out[0] = 10.f * l2 + 10.f * l3;
}

// ---------------------------------------------------------------------------
// Host: MT19937 (numpy legacy) for pair selection
// ---------------------------------------------------------------------------
namespace {
struct HostMT { uint32_t mt[624]; int pos; };
static void mt_seed(HostMT& s, uint32_t seed) {
    for (int p = 0; p < 624; p++) {
        s.mt[p] = seed;
        seed = 1812433253u * (seed ^ (seed >> 30)) + (uint32_t)p + 1u;
    }
    s.pos = 624;
}
static uint32_t mt_next(HostMT& s) {
    if (s.pos == 624) {
        for (int i = 0; i < 624; i++) {
            uint32_t y = (s.mt[i] & 0x80000000u) | (s.mt[(i + 1) % 624] & 0x7fffffffu);
            s.mt[i] = s.mt[(i + 397) % 624] ^ (y >> 1) ^ ((y & 1u) ? 0x9908b0dfu : 0u);
        }
        s.pos = 0;
    }
    uint32_t y = s.mt[s.pos++];
    y ^= y >> 11;
    y ^= (y << 7) & 0x9d2c5680u;
    y ^= (y << 15) & 0xefc60000u;
    y ^= y >> 18;
    return y;
}
static uint32_t mt_interval(HostMT& s, uint32_t mx) {   // uniform in [0, mx]
    if (mx == 0) return 0;
    uint32_t mask = mx;
    mask |= mask >> 1; mask |= mask >> 2; mask |= mask >> 4;
    mask |= mask >> 8; mask |= mask >> 16;
    uint32_t v;
    while ((v = (mt_next(s) & mask)) > mx) {}
    return v;
}
static void perm12(uint32_t seed, int* out) {
    HostMT s; mt_seed(s, seed);
    for (int i = 0; i < 12; i++) out[i] = i;
    for (int i = 11; i > 0; i--) {
        int j = (int)mt_interval(s, (uint32_t)i);
        int t = out[i]; out[i] = out[j]; out[j] = t;
    }
}
}  // namespace

// ---------------------------------------------------------------------------
// kernel_launch
// ---------------------------------------------------------------------------
extern "C" void kernel_launch(void* const* d_in, const int* in_sizes, int n_in,
                              void* d_out, int out_size) {
    const float* z1 = (const float*)d_in[0];
    const float* z2 = (const float*)d_in[1];
    float* out = (float*)d_out;

    float *z1n, *z2n, *sq, *S, *rowbuf, *cntbuf, *slots;
    int *neighCB, *negCB, *neighA, *bofa, *aofb, *idxB, *match, *order, *negc;
    cudaGetSymbolAddress((void**)&z1n, g_z1n);
    cudaGetSymbolAddress((void**)&z2n, g_z2n);
    cudaGetSymbolAddress((void**)&sq, g_sq);
    cudaGetSymbolAddress((void**)&S, g_S);
    cudaGetSymbolAddress((void**)&rowbuf, g_rowbuf);
    cudaGetSymbolAddress((void**)&cntbuf, g_cntbuf);
    cudaGetSymbolAddress((void**)&slots, g_slots);
    cudaGetSymbolAddress((void**)&neighCB, g_neighCB);
    cudaGetSymbolAddress((void**)&negCB, g_negCB);
    cudaGetSymbolAddress((void**)&neighA, g_neighA);
    cudaGetSymbolAddress((void**)&bofa, g_bofa);
    cudaGetSymbolAddress((void**)&aofb, g_aofb);
    cudaGetSymbolAddress((void**)&idxB, g_idxB);
    cudaGetSymbolAddress((void**)&match, g_match);
    cudaGetSymbolAddress((void**)&order, g_order);
    cudaGetSymbolAddress((void**)&negc, g_negc);

    // --- key derivation (partitionable threefry): child i of split = TF(key,(0,i))
    uint32_t ck[4][2];
    for (int i = 0; i < 4; i++)
        threefry2x32(0u, 42u, 0u, (uint32_t)i, ck[i][0], ck[i][1]);
    uint32_t cbk[2][4][2];
    for (int b = 0; b < 4; b++) {
        threefry2x32(ck[0][0], ck[0][1], 0u, (uint32_t)b, cbk[0][b][0], cbk[0][b][1]);
        threefry2x32(ck[1][0], ck[1][1], 0u, (uint32_t)b, cbk[1][b][0], cbk[1][b][1]);
    }
    uint32_t kp[12][2];
    for (int j = 0; j < 6; j++) {
        threefry2x32(ck[2][0], ck[2][1], 0u, (uint32_t)j, kp[j][0], kp[j][1]);
        threefry2x32(ck[3][0], ck[3][1], 0u, (uint32_t)j, kp[6 + j][0], kp[6 + j][1]);
    }

    // --- pair selection (numpy MT19937, seeds 0 and 1)
    int allp[12][2];
    { int t = 0;
      for (int p = 0; p < 4; p++)
          for (int q = 0; q < 4; q++)
              if (p != q) { allp[t][0] = p; allp[t][1] = q; t++; } }
    int pairs[12][2];
    int perm[12];
    perm12(0u, perm);
    for (int j = 0; j < 6; j++) { pairs[j][0] = allp[perm[j]][0]; pairs[j][1] = allp[perm[j]][1]; }
    perm12(1u, perm);
    for (int j = 0; j < 6; j++) { pairs[6 + j][0] = allp[perm[j]][0]; pairs[6 + j][1] = allp[perm[j]][1]; }

    const size_t MAT = (size_t)NT * CD;

    // --- normalize + squared norms
    normalize_kernel<<<2048, 256>>>(z1, z2);

    // --- crossbrain: 8 combos
    for (int d = 0; d < 2; d++) {
        for (int b = 0; b < 4; b++) {
            const float* Araw = (d == 0 ? z1 : z2) + (size_t)b * MAT;
            const float* anch = (d == 0 ? z2n : z1n) + (size_t)b * MAT;
            const float* sqp = sq + d * 4 * NT + b * NT;
            gemm_kernel<<<dim3(16, 16), 256>>>(Araw, Araw, sqp, sqp, S, 0);
            select6_kernel<<<256, 256>>>(S, neighCB);
            cbneg_kernel<<<256, 256>>>(cbk[d][b][0], cbk[d][b][1], neighCB, negCB);
            cbloss_kernel<<<256, 256>>>(anch, neighCB, negCB, rowbuf);
            reduce_kernel<<<1, 1024>>>(rowbuf, slots + d * 4 + b, 1.0f / 10240.0f);
        }
    }

    // --- DA neighbor cache (cos-dist self KNN of A side), dedup across pairs
    bool need[8] = {false, false, false, false, false, false, false, false};
    for (int pi = 0; pi < 12; pi++) need[(pi / 6) * 4 + pairs[pi][0]] = true;
    for (int s = 0; s < 8; s++) {
        if (!need[s]) continue;
        const float* An = (s < 4 ? z1n : z2n) + (size_t)(s & 3) * MAT;
        gemm_kernel<<<dim3(16, 16), 256>>>(An, An, sq, sq, S, 1);
        select6_kernel<<<256, 256>>>(S, neighA + (size_t)s * NT * 5);
    }

    // --- NRC: 12 pair combos
    for (int pi = 0; pi < 12; pi++) {
        int side = pi / 6, p = pairs[pi][0], q = pairs[pi][1];
        const float* An = (side == 0 ? z1n : z2n) + (size_t)p * MAT;
        const float* Bn = (side == 0 ? z2n : z1n) + (size_t)q * MAT;
        gemm_kernel<<<dim3(16, 16), 256>>>(An, Bn, sq, sq, S, 1);
        argmin_rows_kernel<<<256, 256>>>(S, bofa);
        argmin_cols_kernel<<<64, dim3(32, 32)>>>(S, aofb);
        mutual_a_kernel<<<8, 256>>>(bofa, aofb, idxB, match);
        mutual_b_kernel<<<8, 256>>>(idxB, match);
        order_kernel<<<1, 256>>>(match, order, negc);
        nrcloss_kernel<<<256, 256>>>(Bn, idxB, neighA + (size_t)((side * 4 + p)) * NT * 5,
                                     order, negc, kp[pi][0], kp[pi][1], rowbuf, cntbuf);
        reduce_kernel<<<1, 1024>>>(rowbuf, slots + 8 + pi, 1.0f);
        reduce_kernel<<<1, 1024>>>(cntbuf, slots + 20 + pi, 1.0f);
    }

    // --- combine
    final_kernel<<<1, 1>>>(out);
}

// round 8
// speedup vs baseline: 1.3351x; 1.3285x over previous
#include <cuda_runtime.h>
#include <cstdint>

#define NT 2048
#define CD 768
#define INFF  __int_as_float(0x7f800000)
#define NINFF __int_as_float(0xff800000)

// ---------------------------------------------------------------------------
__device__ float g_z1n[4 * NT * CD];
__device__ float g_z2n[4 * NT * CD];
__device__ float g_sq[2 * 4 * NT];
__device__ float g_inv[2 * 4 * NT];
__device__ float g_S[NT * NT];
__device__ int   g_neighCB[NT * 5];
__device__ int   g_negCB[NT * 5];
__device__ int   g_neighA[8 * NT * 5];
__device__ int   g_bofa[NT];
__device__ int   g_aofb[NT];
__device__ int   g_idxB[NT];
__device__ int   g_order[NT];
__device__ int   g_negc;
__device__ float g_rowbuf[NT];
__device__ float g_cntbuf[NT];
__device__ float g_slots[32];

// ---------------------------------------------------------------------------
__host__ __device__ __forceinline__ void threefry2x32(
    uint32_t k0, uint32_t k1, uint32_t c0, uint32_t c1, uint32_t& o0, uint32_t& o1)
{
    uint32_t ks2 = k0 ^ k1 ^ 0x1BD11BDAu;
    uint32_t x0 = c0 + k0, x1 = c1 + k1;
#define TF_R(r) { x0 += x1; x1 = (x1 << (r)) | (x1 >> (32 - (r))); x1 ^= x0; }
    TF_R(13) TF_R(15) TF_R(26) TF_R(6)
    x0 += k1;  x1 += ks2 + 1u;
    TF_R(17) TF_R(29) TF_R(16) TF_R(24)
    x0 += ks2; x1 += k0 + 2u;
    TF_R(13) TF_R(15) TF_R(26) TF_R(6)
    x0 += k0;  x1 += k1 + 3u;
    TF_R(17) TF_R(29) TF_R(16) TF_R(24)
    x0 += k1;  x1 += ks2 + 4u;
    TF_R(13) TF_R(15) TF_R(26) TF_R(6)
    x0 += ks2; x1 += k0 + 5u;
#undef TF_R
    o0 = x0; o1 = x1;
}
__host__ __device__ __forceinline__ uint32_t tf_bits(uint32_t k0, uint32_t k1, uint32_t idx) {
    uint32_t o0, o1;
    threefry2x32(k0, k1, 0u, idx, o0, o1);
    return o0 ^ o1;
}

// ---------------------------------------------------------------------------
// Normalize rows + squared norm + inverse norm. One warp per row.
// ---------------------------------------------------------------------------
__global__ void normalize_kernel(const float* __restrict__ z1,
                                 const float* __restrict__ z2) {
    int gw = (blockIdx.x * blockDim.x + threadIdx.x) >> 5;
    int lane = threadIdx.x & 31;
    if (gw >= 2 * 4 * NT) return;
    const float* src;
    float* dst;
    if (gw < 4 * NT) { src = z1 + (size_t)gw * CD; dst = g_z1n + (size_t)gw * CD; }
    else { int r = gw - 4 * NT; src = z2 + (size_t)r * CD; dst = g_z2n + (size_t)r * CD; }
    float a[24];
    float s = 0.f;
#pragma unroll
    for (int u = 0; u < 24; u++) { float v = src[lane + u * 32]; a[u] = v; s += v * v; }
#pragma unroll
    for (int off = 16; off; off >>= 1) s += __shfl_xor_sync(0xffffffffu, s, off);
    float inv = rsqrtf(s + 1e-12f);
    if (lane == 0) { g_sq[gw] = s; g_inv[gw] = inv; }
#pragma unroll
    for (int u = 0; u < 24; u++) dst[lane + u * 32] = a[u] * inv;
}

// ---------------------------------------------------------------------------
// GEMM with packed f32x2 FMA: S[i,j] = dot(A_i, B_j) raw (no transform).
// 128x128 tile, BK=16, 256 threads, 8x8 per thread (stored as 8x4 f32x2).
// ---------------------------------------------------------------------------
__global__ __launch_bounds__(256, 2) void gemm_kernel(
    const float* __restrict__ A, const float* __restrict__ B,
    float* __restrict__ S)
{
    __shared__ float As[16][128];
    __shared__ float Bs[16][128];

    int tid = threadIdx.x;
    int tx = tid & 15, ty = tid >> 4;
    int lr = tid >> 2, lc = (tid & 3) << 2;

    const float* Ag = A + (size_t)(blockIdx.y * 128) * CD;
    const float* Bg = B + (size_t)(blockIdx.x * 128) * CD;

    unsigned long long acc2[8][4];
#pragma unroll
    for (int i = 0; i < 8; i++)
#pragma unroll
        for (int j = 0; j < 4; j++) acc2[i][j] = 0ull;

    for (int kk = 0; kk < CD; kk += 16) {
        float4 a0 = *(const float4*)(Ag + (size_t)lr * CD + kk + lc);
        float4 a1 = *(const float4*)(Ag + (size_t)(lr + 64) * CD + kk + lc);
        float4 b0 = *(const float4*)(Bg + (size_t)lr * CD + kk + lc);
        float4 b1 = *(const float4*)(Bg + (size_t)(lr + 64) * CD + kk + lc);
        __syncthreads();
        As[lc + 0][lr] = a0.x; As[lc + 1][lr] = a0.y; As[lc + 2][lr] = a0.z; As[lc + 3][lr] = a0.w;
        As[lc + 0][lr + 64] = a1.x; As[lc + 1][lr + 64] = a1.y; As[lc + 2][lr + 64] = a1.z; As[lc + 3][lr + 64] = a1.w;
        Bs[lc + 0][lr] = b0.x; Bs[lc + 1][lr] = b0.y; Bs[lc + 2][lr] = b0.z; Bs[lc + 3][lr] = b0.w;
        Bs[lc + 0][lr + 64] = b1.x; Bs[lc + 1][lr + 64] = b1.y; Bs[lc + 2][lr + 64] = b1.z; Bs[lc + 3][lr + 64] = b1.w;
        __syncthreads();
#pragma unroll
        for (int k = 0; k < 16; k++) {
            float4 av0 = *(const float4*)(&As[k][ty * 8]);
            float4 av1 = *(const float4*)(&As[k][ty * 8 + 4]);
            float ar[8] = {av0.x, av0.y, av0.z, av0.w, av1.x, av1.y, av1.z, av1.w};
            const ulonglong2* bpq = (const ulonglong2*)(&Bs[k][tx * 8]);
            ulonglong2 bq0 = bpq[0], bq1 = bpq[1];
            unsigned long long bp[4] = {bq0.x, bq0.y, bq1.x, bq1.y};
#pragma unroll
            for (int i = 0; i < 8; i++) {
                unsigned long long ai;
                asm("mov.b64 %0, {%1, %1};" : "=l"(ai) : "f"(ar[i]));
#pragma unroll
                for (int j = 0; j < 4; j++)
                    asm("fma.rn.f32x2 %0, %1, %2, %0;" : "+l"(acc2[i][j]) : "l"(ai), "l"(bp[j]));
            }
        }
    }

    int rb = blockIdx.y * 128 + ty * 8;
    int cb = blockIdx.x * 128 + tx * 8;
#pragma unroll
    for (int i = 0; i < 8; i++) {
        float o[8];
#pragma unroll
        for (int j = 0; j < 4; j++)
            asm("mov.b64 {%0, %1}, %2;" : "=f"(o[2 * j]), "=f"(o[2 * j + 1]) : "l"(acc2[i][j]));
        float4* dst = (float4*)(S + (size_t)(rb + i) * NT + cb);
        dst[0] = make_float4(o[0], o[1], o[2], o[3]);
        dst[1] = make_float4(o[4], o[5], o[6], o[7]);
    }
}

// ---------------------------------------------------------------------------
// select6: 6 smallest per row of transformed raw dot, stable ties; emit 1..5.
// mode 0: v = max(sq_i + sq_j - 2*dot, 0)    mode 1: v = 1 - dot*inv_i*inv_j
// ---------------------------------------------------------------------------
__global__ void select6_kernel(const float* __restrict__ S, int* __restrict__ neigh,
                               int mode, const float* __restrict__ sqv,
                               const float* __restrict__ invv) {
    int row = (blockIdx.x * blockDim.x + threadIdx.x) >> 5;
    int lane = threadIdx.x & 31;
    if (row >= NT) return;
    const float* r = S + (size_t)row * NT;
    float me = mode ? invv[row] : sqv[row];

    float bv[6]; int bi[6];
#pragma unroll
    for (int u = 0; u < 6; u++) { bv[u] = INFF; bi[u] = 0x7fffffff; }
    for (int j = lane; j < NT; j += 32) {
        float dot = r[j];
        float v = mode ? (1.f - dot * me * invv[j]) : fmaxf(me + sqv[j] - 2.f * dot, 0.f);
        if (v < bv[5] || (v == bv[5] && j < bi[5])) {
            int pos = 5;
            while (pos > 0 && (v < bv[pos - 1] || (v == bv[pos - 1] && j < bi[pos - 1]))) {
                bv[pos] = bv[pos - 1]; bi[pos] = bi[pos - 1]; pos--;
            }
            bv[pos] = v; bi[pos] = j;
        }
    }
    for (int t = 0; t < 6; t++) {
        float v = bv[0]; int id = bi[0];
#pragma unroll
        for (int off = 16; off; off >>= 1) {
            float ov = __shfl_down_sync(0xffffffffu, v, off);
            int oi = __shfl_down_sync(0xffffffffu, id, off);
            if (ov < v || (ov == v && oi < id)) { v = ov; id = oi; }
        }
        id = __shfl_sync(0xffffffffu, id, 0);
        if (bi[0] == id) {
#pragma unroll
            for (int u = 0; u < 5; u++) { bv[u] = bv[u + 1]; bi[u] = bi[u + 1]; }
            bv[5] = INFF; bi[5] = 0x7fffffff;
        }
        if (t > 0 && lane == 0) neigh[row * 5 + t - 1] = id;
    }
}

// ---------------------------------------------------------------------------
// cbneg: top-5 largest uniforms per row, 4 warps per row (grid NT, block 128).
// ---------------------------------------------------------------------------
__global__ void cbneg_kernel(uint32_t k0, uint32_t k1,
                             const int* __restrict__ neigh, int* __restrict__ neg) {
    __shared__ float sv[20];
    __shared__ int   si[20];
    int row = blockIdx.x;
    int wid = threadIdx.x >> 5, lane = threadIdx.x & 31;
    int n0 = neigh[row * 5 + 0], n1 = neigh[row * 5 + 1], n2 = neigh[row * 5 + 2],
        n3 = neigh[row * 5 + 3], n4 = neigh[row * 5 + 4];
    float bv[5]; int bi[5];
#pragma unroll
    for (int u = 0; u < 5; u++) { bv[u] = NINFF; bi[u] = 0x7fffffff; }
    int jend = wid * 512 + 512;
    for (int j = wid * 512 + lane; j < jend; j += 32) {
        if (j == row || j == n0 || j == n1 || j == n2 || j == n3 || j == n4) continue;
        uint32_t bits = tf_bits(k0, k1, (uint32_t)(row * NT + j));
        float v = __uint_as_float((bits >> 9) | 0x3f800000u) - 1.0f;
        if (v > bv[4] || (v == bv[4] && j < bi[4])) {
            int pos = 4;
            while (pos > 0 && (v > bv[pos - 1] || (v == bv[pos - 1] && j < bi[pos - 1]))) {
                bv[pos] = bv[pos - 1]; bi[pos] = bi[pos - 1]; pos--;
            }
            bv[pos] = v; bi[pos] = j;
        }
    }
    for (int t = 0; t < 5; t++) {
        float v = bv[0]; int id = bi[0];
#pragma unroll
        for (int off = 16; off; off >>= 1) {
            float ov = __shfl_down_sync(0xffffffffu, v, off);
            int oi = __shfl_down_sync(0xffffffffu, id, off);
            if (ov > v || (ov == v && oi < id)) { v = ov; id = oi; }
        }
        v = __shfl_sync(0xffffffffu, v, 0);
        id = __shfl_sync(0xffffffffu, id, 0);
        if (bi[0] == id) {
#pragma unroll
            for (int u = 0; u < 4; u++) { bv[u] = bv[u + 1]; bi[u] = bi[u + 1]; }
            bv[4] = NINFF; bi[4] = 0x7fffffff;
        }
        if (lane == 0) { sv[wid * 5 + t] = v; si[wid * 5 + t] = id; }
    }
    __syncthreads();
    if (wid == 0) {
        float v = (lane < 20) ? sv[lane] : NINFF;
        int id = (lane < 20) ? si[lane] : 0x7fffffff;
        for (int t = 0; t < 5; t++) {
            float wv = v; int wi = id;
#pragma unroll
            for (int off = 16; off; off >>= 1) {
                float ov = __shfl_down_sync(0xffffffffu, wv, off);
                int oi = __shfl_down_sync(0xffffffffu, wi, off);
                if (ov > wv || (ov == wv && oi < wi)) { wv = ov; wi = oi; }
            }
            wi = __shfl_sync(0xffffffffu, wi, 0);
            if (id == wi) { v = NINFF; id = 0x7fffffff; }
            if (lane == 0) neg[row * 5 + t] = wi;
        }
    }
}

// ---------------------------------------------------------------------------
__global__ void cbloss_kernel(const float* __restrict__ An,
                              const int* __restrict__ neigh,
                              const int* __restrict__ neg,
                              float* __restrict__ rowbuf) {
    int row = (blockIdx.x * blockDim.x + threadIdx.x) >> 5;
    int lane = threadIdx.x & 31;
    if (row >= NT) return;
    float a[24];
    const float* ar = An + (size_t)row * CD;
#pragma unroll
    for (int u = 0; u < 24; u++) a[u] = ar[lane + u * 32];
    float s = 0.f;
    for (int k = 0; k < 5; k++) {
        const float* pr = An + (size_t)neigh[row * 5 + k] * CD;
        const float* nr = An + (size_t)neg[row * 5 + k] * CD;
        float dp = 0.f, dn = 0.f;
#pragma unroll
        for (int u = 0; u < 24; u++) {
            dp += a[u] * pr[lane + u * 32];
            dn += a[u] * nr[lane + u * 32];
        }
#pragma unroll
        for (int off = 16; off; off >>= 1) {
            dp += __shfl_xor_sync(0xffffffffu, dp, off);
            dn += __shfl_xor_sync(0xffffffffu, dn, off);
        }
        float sp = fminf(fmaxf(dp, -1.f), 1.f);
        float sn = fminf(fmaxf(dn, -1.f), 1.f);
        s += fmaxf(sn - sp + 0.05f, 0.f);
    }
    if (lane == 0) rowbuf[row] = s;
}

// ---------------------------------------------------------------------------
__global__ void argmin_rows_kernel(const float* __restrict__ S, int* __restrict__ out) {
    int row = (blockIdx.x * blockDim.x + threadIdx.x) >> 5;
    int lane = threadIdx.x & 31;
    if (row >= NT) return;
    const float* r = S + (size_t)row * NT;
    float bv = INFF; int bi = 0x7fffffff;
    for (int j = lane; j < NT; j += 32) {
        float v = 1.f - r[j];
        if (v < bv || (v == bv && j < bi)) { bv = v; bi = j; }
    }
#pragma unroll
    for (int off = 16; off; off >>= 1) {
        float ov = __shfl_down_sync(0xffffffffu, bv, off);
        int oi = __shfl_down_sync(0xffffffffu, bi, off);
        if (ov < bv || (ov == bv && oi < bi)) { bv = ov; bi = oi; }
    }
    if (lane == 0) out[row] = bi;
}

__global__ void argmin_cols_kernel(const float* __restrict__ S, int* __restrict__ out) {
    __shared__ float sv[32][33];
    __shared__ int   si[32][33];
    int tx = threadIdx.x, ty = threadIdx.y;
    int c = blockIdx.x * 32 + tx;
    float bv = INFF; int bi = 0x7fffffff;
    for (int r0 = 0; r0 < NT; r0 += 32) {
        int r = r0 + ty;
        float v = 1.f - S[(size_t)r * NT + c];
        if (v < bv || (v == bv && r < bi)) { bv = v; bi = r; }
    }
    sv[ty][tx] = bv; si[ty][tx] = bi;
    __syncthreads();
    if (ty == 0) {
        float v = sv[0][tx]; int id = si[0][tx];
#pragma unroll
        for (int u = 1; u < 32; u++) {
            float ov = sv[u][tx]; int oi = si[u][tx];
            if (ov < v || (ov == v && oi < id)) { v = ov; id = oi; }
        }
        out[c] = id;
    }
}

// ---------------------------------------------------------------------------
// Fused mutual matching + stable bool partition (unmatched first).
// Single block, 256 threads.
// ---------------------------------------------------------------------------
__global__ void mutual_order_kernel(const int* __restrict__ bofa,
                                    const int* __restrict__ aofb,
                                    int* __restrict__ idxB, int* __restrict__ order,
                                    int* __restrict__ negc) {
    __shared__ int matchs[NT];
    __shared__ int cnt[256];
    __shared__ int excl[257];
    int t = threadIdx.x;
    for (int i = t; i < NT; i += 256) matchs[i] = 0;
    __syncthreads();
    int base = t * 8;
#pragma unroll
    for (int u = 0; u < 8; u++) {
        int i = base + u;
        int b = bofa[i];
        int v = (aofb[b] == i) ? b : -1;
        idxB[i] = v;
        if (v >= 0) matchs[v] = 1;
    }
    __syncthreads();
    int m[8]; int c = 0;
#pragma unroll
    for (int u = 0; u < 8; u++) { m[u] = matchs[base + u]; c += (m[u] == 0); }
    cnt[t] = c;
    __syncthreads();
    if (t == 0) {
        int s = 0;
        for (int i = 0; i < 256; i++) { excl[i] = s; s += cnt[i]; }
        excl[256] = s;
    }
    __syncthreads();
    int Utot = excl[256];
    int u = excl[t];
    int mm = base - u;
#pragma unroll
    for (int x = 0; x < 8; x++) {
        if (m[x] == 0) order[u++] = base + x;
        else           order[Utot + mm++] = base + x;
    }
    if (t == 0) *negc = (Utot > 0) ? Utot : 1;
}

// ---------------------------------------------------------------------------
__global__ void nrcloss_kernel(const float* __restrict__ Bn,
                               const int* __restrict__ idxB,
                               const int* __restrict__ neighA,
                               const int* __restrict__ order,
                               const int* __restrict__ negcp,
                               uint32_t k0, uint32_t k1,
                               float* __restrict__ rowbuf, float* __restrict__ cntbuf) {
    int i = (blockIdx.x * blockDim.x + threadIdx.x) >> 5;
    int lane = threadIdx.x & 31;
    if (i >= NT) return;
    int ib = idxB[i];
    int uB = ib < 0 ? 0 : ib;
    int nc = *negcp;
    float a[24];
    const float* ar = Bn + (size_t)uB * CD;
#pragma unroll
    for (int u = 0; u < 24; u++) a[u] = ar[lane + u * 32];
    float hs = 0.f; int npos = 0;
    for (int k = 0; k < 5; k++) {
        int pb = idxB[neighA[i * 5 + k]];
        uint32_t bits = tf_bits(k0, k1, 10240u + (uint32_t)(i * 5 + k));
        int nb = order[(int)(bits & 2047u) % nc];
        const float* pr = Bn + (size_t)(pb < 0 ? 0 : pb) * CD;
        const float* nr = Bn + (size_t)nb * CD;
        float dp = 0.f, dn = 0.f;
#pragma unroll
        for (int u = 0; u < 24; u++) {
            dp += a[u] * pr[lane + u * 32];
            dn += a[u] * nr[lane + u * 32];
        }
#pragma unroll
        for (int off = 16; off; off >>= 1) {
            dp += __shfl_xor_sync(0xffffffffu, dp, off);
            dn += __shfl_xor_sync(0xffffffffu, dn, off);
        }
        if (pb >= 0) { hs += fmaxf(dn - dp + 0.4f, 0.f); npos++; }
    }
    if (lane == 0) {
        float per = hs / (float)(npos > 0 ? npos : 1);
        int valid = (ib >= 0) && (npos > 0);
        rowbuf[i] = valid ? per : 0.f;
        cntbuf[i] = valid ? 1.f : 0.f;
    }
}

// ---------------------------------------------------------------------------
__global__ void reduce_kernel(const float* __restrict__ buf, float* __restrict__ dst, float scale) {
    __shared__ float sh[1024];
    int t = threadIdx.x;
    sh[t] = buf[t] + buf[t + 1024];
    __syncthreads();
    for (int s = 512; s; s >>= 1) {
        if (t < s) sh[t] += sh[t + s];
        __syncthreads();
    }
    if (t == 0) *dst = sh[0] * scale;
}

__global__ void final_kernel(float* __restrict__ out) {
    float l2 = 0.f;
    for (int i = 0; i < 8; i++) l2 += g_slots[i];
    l2 *= 0.25f;
    float l3 = 0.f;
    for (int s = 0; s < 2; s++) {
        float acc = 0.f;
        for (int j = 0; j < 6; j++) {
            int pi = s * 6 + j;
            float cn = g_slots[20 + pi];
            float sm = g_slots[8 + pi];
            acc += (cn > 0.f) ? sm / fmaxf(cn, 1.f) : 0.f;
        }
        l3 += acc / 6.f;
    }
    out[0] = 10.f * l2 + 10.f * l3;
}

// ---------------------------------------------------------------------------
namespace {
struct HostMT { uint32_t mt[624]; int pos; };
static void mt_seed(HostMT& s, uint32_t seed) {
    for (int p = 0; p < 624; p++) {
        s.mt[p] = seed;
        seed = 1812433253u * (seed ^ (seed >> 30)) + (uint32_t)p + 1u;
    }
    s.pos = 624;
}
static uint32_t mt_next(HostMT& s) {
    if (s.pos == 624) {
        for (int i = 0; i < 624; i++) {
            uint32_t y = (s.mt[i] & 0x80000000u) | (s.mt[(i + 1) % 624] & 0x7fffffffu);
            s.mt[i] = s.mt[(i + 397) % 624] ^ (y >> 1) ^ ((y & 1u) ? 0x9908b0dfu : 0u);
        }
        s.pos = 0;
    }
    uint32_t y = s.mt[s.pos++];
    y ^= y >> 11;
    y ^= (y << 7) & 0x9d2c5680u;
    y ^= (y << 15) & 0xefc60000u;
    y ^= y >> 18;
    return y;
}
static uint32_t mt_interval(HostMT& s, uint32_t mx) {
    if (mx == 0) return 0;
    uint32_t mask = mx;
    mask |= mask >> 1; mask |= mask >> 2; mask |= mask >> 4;
    mask |= mask >> 8; mask |= mask >> 16;
    uint32_t v;
    while ((v = (mt_next(s) & mask)) > mx) {}
    return v;
}
static void perm12(uint32_t seed, int* out) {
    HostMT s; mt_seed(s, seed);
    for (int i = 0; i < 12; i++) out[i] = i;
    for (int i = 11; i > 0; i--) {
        int j = (int)mt_interval(s, (uint32_t)i);
        int t = out[i]; out[i] = out[j]; out[j] = t;
    }
}
}  // namespace

// ---------------------------------------------------------------------------
extern "C" void kernel_launch(void* const* d_in, const int* in_sizes, int n_in,
                              void* d_out, int out_size) {
    const float* z1 = (const float*)d_in[0];
    const float* z2 = (const float*)d_in[1];
    float* out = (float*)d_out;

    float *z1n, *z2n, *sq, *invv, *S, *rowbuf, *cntbuf, *slots;
    int *neighCB, *negCB, *neighA, *bofa, *aofb, *idxB, *order, *negc;
    cudaGetSymbolAddress((void**)&z1n, g_z1n);
    cudaGetSymbolAddress((void**)&z2n, g_z2n);
    cudaGetSymbolAddress((void**)&sq, g_sq);
    cudaGetSymbolAddress((void**)&invv, g_inv);
    cudaGetSymbolAddress((void**)&S, g_S);
    cudaGetSymbolAddress((void**)&rowbuf, g_rowbuf);
    cudaGetSymbolAddress((void**)&cntbuf, g_cntbuf);
    cudaGetSymbolAddress((void**)&slots, g_slots);
    cudaGetSymbolAddress((void**)&neighCB, g_neighCB);
    cudaGetSymbolAddress((void**)&negCB, g_negCB);
    cudaGetSymbolAddress((void**)&neighA, g_neighA);
    cudaGetSymbolAddress((void**)&bofa, g_bofa);
    cudaGetSymbolAddress((void**)&aofb, g_aofb);
    cudaGetSymbolAddress((void**)&idxB, g_idxB);
    cudaGetSymbolAddress((void**)&order, g_order);
    cudaGetSymbolAddress((void**)&negc, g_negc);

    uint32_t ck[4][2];
    for (int i = 0; i < 4; i++)
        threefry2x32(0u, 42u, 0u, (uint32_t)i, ck[i][0], ck[i][1]);
    uint32_t cbk[2][4][2];
    for (int b = 0; b < 4; b++) {
        threefry2x32(ck[0][0], ck[0][1], 0u, (uint32_t)b, cbk[0][b][0], cbk[0][b][1]);
        threefry2x32(ck[1][0], ck[1][1], 0u, (uint32_t)b, cbk[1][b][0], cbk[1][b][1]);
    }
    uint32_t kp[12][2];
    for (int j = 0; j < 6; j++) {
        threefry2x32(ck[2][0], ck[2][1], 0u, (uint32_t)j, kp[j][0], kp[j][1]);
        threefry2x32(ck[3][0], ck[3][1], 0u, (uint32_t)j, kp[6 + j][0], kp[6 + j][1]);
    }

    int allp[12][2];
    { int t = 0;
      for (int p = 0; p < 4; p++)
          for (int q = 0; q < 4; q++)
              if (p != q) { allp[t][0] = p; allp[t][1] = q; t++; } }
    int pairs[12][2];
    int perm[12];
    perm12(0u, perm);
    for (int j = 0; j < 6; j++) { pairs[j][0] = allp[perm[j]][0]; pairs[j][1] = allp[perm[j]][1]; }
    perm12(1u, perm);
    for (int j = 0; j < 6; j++) { pairs[6 + j][0] = allp[perm[j]][0]; pairs[6 + j][1] = allp[perm[j]][1]; }

    const size_t MAT = (size_t)NT * CD;

    normalize_kernel<<<2048, 256>>>(z1, z2);

    bool needA[8];
    for (int s = 0; s < 8; s++) needA[s] = false;
    for (int pi = 0; pi < 12; pi++) needA[(pi / 6) * 4 + pairs[pi][0]] = true;

    // --- self GEMMs on raw vectors: serve crossbrain (sq-dist) + DA cache (cos)
    for (int s = 0; s < 8; s++) {
        int d = s >> 2, b = s & 3;
        const float* Araw = (d == 0 ? z1 : z2) + (size_t)b * MAT;
        const float* anch = (d == 0 ? z2n : z1n) + (size_t)b * MAT;
        const float* sqp = sq + (size_t)s * NT;
        const float* invp = invv + (size_t)s * NT;
        gemm_kernel<<<dim3(16, 16), 256>>>(Araw, Araw, S);
        select6_kernel<<<256, 256>>>(S, neighCB, 0, sqp, invp);
        if (needA[s]) select6_kernel<<<256, 256>>>(S, neighA + (size_t)s * NT * 5, 1, sqp, invp);
        cbneg_kernel<<<NT, 128>>>(cbk[d][b][0], cbk[d][b][1], neighCB, negCB);
        cbloss_kernel<<<256, 256>>>(anch, neighCB, negCB, rowbuf);
        reduce_kernel<<<1, 1024>>>(rowbuf, slots + s, 1.0f / 10240.0f);
    }

    // --- NRC: 12 pair combos (normalized vectors, raw dots in S)
    for (int pi = 0; pi < 12; pi++) {
        int side = pi / 6, p = pairs[pi][0], q = pairs[pi][1];
        const float* An = (side == 0 ? z1n : z2n) + (size_t)p * MAT;
        const float* Bn = (side == 0 ? z2n : z1n) + (size_t)q * MAT;
        gemm_kernel<<<dim3(16, 16), 256>>>(An, Bn, S);
        argmin_rows_kernel<<<256, 256>>>(S, bofa);
        argmin_cols_kernel<<<64, dim3(32, 32)>>>(S, aofb);
        mutual_order_kernel<<<1, 256>>>(bofa, aofb, idxB, order, negc);
        nrcloss_kernel<<<256, 256>>>(Bn, idxB, neighA + (size_t)(side * 4 + p) * NT * 5,
                                     order, negc, kp[pi][0], kp[pi][1], rowbuf, cntbuf);
        reduce_kernel<<<1, 1024>>>(rowbuf, slots + 8 + pi, 1.0f);
        reduce_kernel<<<1, 1024>>>(cntbuf, slots + 20 + pi, 1.0f);
    }

    final_kernel<<<1, 1>>>(out);
}